// round 5
// baseline (speedup 1.0000x reference)
#include <cuda_runtime.h>
#include <cuda_fp16.h>
#include <math.h>

#define Bb 4
#define Gg 128
#define Nn 2048
#define Pp 4
#define Ff 64
#define BP 16
#define ZTOL 1e-9f
#define NCH 32          // 32 chunks of 64 rows
#define CHR 64
#define MAXNNZ (1 << 19)

// ---------------- scratch ----------------
__device__ __align__(16) __half2 g_Wxh[BP * Nn * (Ff / 2)];  // [bp][m][f/2] 4MB
__device__ __align__(16) float4  g_T1n[Nn * BP];  // [n][bp]: (s1, e^{s1}, e^{.2 s1}, 0)
__device__ __align__(16) float4  g_T2n[Nn * BP];  // [m][bp]: (s2, e^{s2}/D, e^{.2 s2}/D, 0)
__device__ float g_s2n[Nn * BP];                  // [n][bp]
__device__ int   g_cnt[Nn * NCH];
__device__ int   g_off2[Nn * NCH];
__device__ int   g_tot[Nn];
__device__ int   g_colptr[Nn + 1];
__device__ __align__(16) float2 g_rv[MAXNNZ];     // (bits of m*32, S value), col-major order

// ---------------------------------------------------------------------------
// K1: Wx = W @ x per (b,p); writes fp16 Wx + s1/s2 exp tables (fp32 exact).
// ---------------------------------------------------------------------------
__global__ void k1_wx(const float* __restrict__ x, const float* __restrict__ a,
                      const float* __restrict__ W) {
    const int b = blockIdx.z, p = blockIdx.y;
    const int n = blockIdx.x * 256 + threadIdx.x;

    __shared__ __align__(16) float Ws[Gg * Ff];
    __shared__ float as[2 * Ff];

    for (int i = threadIdx.x; i < Gg * Ff; i += 256) {
        int f = i >> 7, g = i & 127;
        Ws[g * Ff + f] = W[(p * Ff + f) * Gg + g];
    }
    if (threadIdx.x < 2 * Ff) as[threadIdx.x] = a[p * 2 * Ff + threadIdx.x];
    __syncthreads();

    float4 acc[16];
#pragma unroll
    for (int i = 0; i < 16; i++) acc[i] = make_float4(0.f, 0.f, 0.f, 0.f);

    const float* xb = x + ((size_t)b * Gg) * Nn + n;
    const float4* Ws4 = (const float4*)Ws;

    for (int g = 0; g < Gg; g++) {
        float xv = xb[(size_t)g * Nn];
#pragma unroll
        for (int i = 0; i < 16; i++) {
            float4 w = Ws4[g * 16 + i];
            acc[i].x += w.x * xv; acc[i].y += w.y * xv;
            acc[i].z += w.z * xv; acc[i].w += w.w * xv;
        }
    }

    const int bp = b * Pp + p;
    __half2* dsth = g_Wxh + (size_t)(bp * Nn + n) * (Ff / 2);
    float s1 = 0.f, s2 = 0.f;
#pragma unroll
    for (int i = 0; i < 16; i++) {
        dsth[2 * i]     = __floats2half2_rn(acc[i].x, acc[i].y);
        dsth[2 * i + 1] = __floats2half2_rn(acc[i].z, acc[i].w);
        s1 += as[4*i+0]*acc[i].x + as[4*i+1]*acc[i].y + as[4*i+2]*acc[i].z + as[4*i+3]*acc[i].w;
        s2 += as[Ff+4*i+0]*acc[i].x + as[Ff+4*i+1]*acc[i].y + as[Ff+4*i+2]*acc[i].z + as[Ff+4*i+3]*acc[i].w;
    }
    g_T1n[n * BP + bp] = make_float4(s1, __expf(s1), __expf(0.2f * s1), 0.f);
    g_s2n[n * BP + bp] = s2;
}

// ---------------------------------------------------------------------------
// K2: softmax denominators per (m,bp) via exp-product tables.
// ---------------------------------------------------------------------------
__global__ void k2_rowstats(const float* __restrict__ S) {
    const int m = blockIdx.x;
    const int tid = threadIdx.x;

    __shared__ float s2s[BP], eas[BP], ebs[BP];
    __shared__ float red[8][BP];
    if (tid < BP) {
        float s2 = g_s2n[m * BP + tid];
        s2s[tid] = s2; eas[tid] = __expf(s2); ebs[tid] = __expf(0.2f * s2);
    }
    __syncthreads();

    float D[BP];
#pragma unroll
    for (int bp = 0; bp < BP; bp++) D[bp] = 0.f;

    const float* row = S + (size_t)m * Nn;
    for (int n = tid; n < Nn; n += 256) {
        float adj = row[n] + (n == m ? 1.f : 0.f);
        if (fabsf(adj) > ZTOL) {
            const float4* t1p = &g_T1n[n * BP];
#pragma unroll
            for (int bp = 0; bp < BP; bp++) {
                float4 t1 = t1p[bp];
                float t = s2s[bp] + t1.x;
                D[bp] += (t >= 0.f) ? eas[bp] * t1.y : ebs[bp] * t1.z;
            }
        }
    }

#pragma unroll
    for (int bp = 0; bp < BP; bp++) {
#pragma unroll
        for (int off = 16; off; off >>= 1)
            D[bp] += __shfl_down_sync(0xffffffffu, D[bp], off);
    }
    const int w = tid >> 5, l = tid & 31;
    if (l == 0) {
#pragma unroll
        for (int bp = 0; bp < BP; bp++) red[w][bp] = D[bp];
    }
    __syncthreads();
    if (tid < BP) {
        float d = 0.f;
#pragma unroll
        for (int ww = 0; ww < 8; ww++) d += red[ww][tid];
        float ci = (d > 0.f) ? 1.f / d : 0.f;
        g_T2n[m * BP + tid] = make_float4(s2s[tid], eas[tid] * ci, ebs[tid] * ci, 0.f);
    }
}

// ---------------------------------------------------------------------------
// K3: deterministic CSC build (counts -> warp-shuffle offsets -> scan -> fill).
// ---------------------------------------------------------------------------
__global__ void k3_count(const float* __restrict__ S) {
    const int n = blockIdx.x * 256 + threadIdx.x;
    const int mc = blockIdx.y;
    int c = 0;
    const int m0 = mc * CHR;
#pragma unroll 8
    for (int mm = 0; mm < CHR; mm++)
        if (fabsf(S[(size_t)(m0 + mm) * Nn + n]) > ZTOL) c++;
    g_cnt[n * NCH + mc] = c;
}

__global__ void k3_offs() {   // warp per column: shuffle scan of 32 chunk counts
    const int n = blockIdx.x * 8 + (threadIdx.x >> 5);
    const int lane = threadIdx.x & 31;
    int c = g_cnt[n * NCH + lane];
    int v = c;
#pragma unroll
    for (int off = 1; off < 32; off <<= 1) {
        int u = __shfl_up_sync(0xffffffffu, v, off);
        if (lane >= off) v += u;
    }
    g_off2[n * NCH + lane] = v - c;
    if (lane == 31) g_tot[n] = v;
}

__global__ void k3_scan() {   // one block: colptr over 2048 totals
    __shared__ int s[Nn];
    const int tid = threadIdx.x;
    const int n0 = tid, n1 = tid + 1024;
    int t0 = g_tot[n0], t1 = g_tot[n1];
    s[n0] = t0; s[n1] = t1;
    __syncthreads();
    for (int off = 1; off < Nn; off <<= 1) {
        int a0 = (n0 >= off) ? s[n0 - off] : 0;
        int a1 = (n1 >= off) ? s[n1 - off] : 0;
        __syncthreads();
        s[n0] += a0; s[n1] += a1;
        __syncthreads();
    }
    g_colptr[n0] = s[n0] - t0;
    g_colptr[n1] = s[n1] - t1;
    if (tid == 1023) g_colptr[Nn] = s[Nn - 1];
}

__global__ void k3_fill(const float* __restrict__ S) {
    const int n = blockIdx.x * 256 + threadIdx.x;
    const int mc = blockIdx.y;
    int off = g_colptr[n] + g_off2[n * NCH + mc];
    const int m0 = mc * CHR;
    for (int mm = 0; mm < CHR; mm++) {
        int m = m0 + mm;
        float sv = S[(size_t)m * Nn + n];
        if (fabsf(sv) > ZTOL && off < MAXNNZ) {
            g_rv[off] = make_float2(__int_as_float(m * (Ff / 2)), sv);
            off++;
        }
    }
}

// ---------------------------------------------------------------------------
// K4: block = column n, 16 warps = bp, lanes = f-pairs.
// One long loop over the column's entries; fused weight computation;
// fp16 Wx gather (128B per warp-entry).
// ---------------------------------------------------------------------------
__global__ void __launch_bounds__(512) k4_out(float* __restrict__ out) {
    const int n = blockIdx.x;
    const int bp = threadIdx.x >> 5;
    const int lane = threadIdx.x & 31;

    const int lo = g_colptr[n], hi = g_colptr[n + 1];
    const float4 t1 = g_T1n[n * BP + bp];
    const __half2* __restrict__ wxh = g_Wxh + (size_t)bp * Nn * (Ff / 2);
    const float4* __restrict__ t2tab = g_T2n;
    const float2* __restrict__ rv = g_rv;

    float a0 = 0.f, a1 = 0.f;
#pragma unroll 4
    for (int i = lo; i < hi; i++) {
        float2 e = rv[i];
        int mo = __float_as_int(e.x);            // m * 32
        float4 t2 = t2tab[mo >> 1 | bp];         // m*16 + bp
        float t = t1.x + t2.x;
        float wgt = e.y * ((t >= 0.f) ? t1.y * t2.y : t1.z * t2.z);
        float2 wx = __half22float2(wxh[mo + lane]);
        a0 = fmaf(wgt, wx.x, a0);
        a1 = fmaf(wgt, wx.y, a1);
    }

    const int b = bp >> 2, p = bp & 3;
    const size_t base = ((size_t)b * (Pp * Ff) + p * Ff) * Nn + n;
    out[base + (size_t)(2 * lane) * Nn]     = fmaxf(a0, 0.f);
    out[base + (size_t)(2 * lane + 1) * Nn] = fmaxf(a1, 0.f);
}

// ---------------------------------------------------------------------------
extern "C" void kernel_launch(void* const* d_in, const int* in_sizes, int n_in,
                              void* d_out, int out_size) {
    const float* x = (const float*)d_in[0];
    const float* a = (const float*)d_in[1];
    const float* W = (const float*)d_in[2];
    const float* S = (const float*)d_in[3];
    float* out = (float*)d_out;

    k1_wx<<<dim3(8, Pp, Bb), 256>>>(x, a, W);
    k3_count<<<dim3(8, NCH), 256>>>(S);
    k3_offs<<<256, 256>>>();
    k3_scan<<<1, 1024>>>();
    k3_fill<<<dim3(8, NCH), 256>>>(S);
    k2_rowstats<<<Nn, 256>>>(S);
    k4_out<<<Nn, 512>>>(out);
}

// round 6
// speedup vs baseline: 1.7914x; 1.7914x over previous
#include <cuda_runtime.h>
#include <cuda_fp16.h>
#include <math.h>

#define Bb 4
#define Gg 128
#define Nn 2048
#define Pp 4
#define Ff 64
#define BP 16
#define ZTOL 1e-9f
#define NCH 32          // 32 chunks of 64 rows
#define CHR 64
#define MAXNNZ (1 << 19)

// ---------------- scratch ----------------
__device__ __align__(16) __half2 g_Wxh[BP * Nn * (Ff / 2)];  // [bp][m][f/2] 4MB
__device__ __align__(16) float4  g_T1n[Nn * BP];  // [n][bp]: (s1, e^{s1}, e^{.2 s1}, 0)
__device__ __align__(16) float4  g_T2n[Nn * BP];  // [m][bp]: (s2, e^{s2}/D, e^{.2 s2}/D, 0)
__device__ float g_s1p[BP * Nn];                  // [bp][n] plane (k2 hot loop)
__device__ float g_s2p[BP * Nn];                  // [bp][n] plane
__device__ int   g_cnt[Nn * NCH];
__device__ int   g_off2[Nn * NCH];
__device__ int   g_tot[Nn];
__device__ int   g_colptr[Nn + 1];
__device__ __align__(16) float2 g_rv[MAXNNZ];     // (bits of m*32, S value), col-major

// ---------------------------------------------------------------------------
// K1: Wx = W @ x per (b,p) -> fp16; s1/s2 planes + T1 exp table.
// ---------------------------------------------------------------------------
__global__ void k1_wx(const float* __restrict__ x, const float* __restrict__ a,
                      const float* __restrict__ W) {
    const int b = blockIdx.z, p = blockIdx.y;
    const int n = blockIdx.x * 256 + threadIdx.x;

    __shared__ __align__(16) float Ws[Gg * Ff];
    __shared__ float as[2 * Ff];

    for (int i = threadIdx.x; i < Gg * Ff; i += 256) {
        int f = i >> 7, g = i & 127;
        Ws[g * Ff + f] = W[(p * Ff + f) * Gg + g];
    }
    if (threadIdx.x < 2 * Ff) as[threadIdx.x] = a[p * 2 * Ff + threadIdx.x];
    __syncthreads();

    float4 acc[16];
#pragma unroll
    for (int i = 0; i < 16; i++) acc[i] = make_float4(0.f, 0.f, 0.f, 0.f);

    const float* xb = x + ((size_t)b * Gg) * Nn + n;
    const float4* Ws4 = (const float4*)Ws;

    for (int g = 0; g < Gg; g++) {
        float xv = xb[(size_t)g * Nn];
#pragma unroll
        for (int i = 0; i < 16; i++) {
            float4 w = Ws4[g * 16 + i];
            acc[i].x += w.x * xv; acc[i].y += w.y * xv;
            acc[i].z += w.z * xv; acc[i].w += w.w * xv;
        }
    }

    const int bp = b * Pp + p;
    __half2* dsth = g_Wxh + (size_t)(bp * Nn + n) * (Ff / 2);
    float s1 = 0.f, s2 = 0.f;
#pragma unroll
    for (int i = 0; i < 16; i++) {
        dsth[2 * i]     = __floats2half2_rn(acc[i].x, acc[i].y);
        dsth[2 * i + 1] = __floats2half2_rn(acc[i].z, acc[i].w);
        s1 += as[4*i+0]*acc[i].x + as[4*i+1]*acc[i].y + as[4*i+2]*acc[i].z + as[4*i+3]*acc[i].w;
        s2 += as[Ff+4*i+0]*acc[i].x + as[Ff+4*i+1]*acc[i].y + as[Ff+4*i+2]*acc[i].z + as[Ff+4*i+3]*acc[i].w;
    }
    g_s1p[bp * Nn + n] = s1;
    g_s2p[bp * Nn + n] = s2;
    g_T1n[n * BP + bp] = make_float4(s1, __expf(s1), __expf(0.2f * s1), 0.f);
}

// ---------------------------------------------------------------------------
// K2: R1's proven denominator loop (scalar plane loads + inline expf under
// the divergent mask), epilogue emits the T2 table for k4's fused weights.
// ---------------------------------------------------------------------------
__global__ void k2_rowstats(const float* __restrict__ S) {
    const int m = blockIdx.x;
    const int tid = threadIdx.x;

    __shared__ float s2s[BP];
    __shared__ float red[8][BP];
    if (tid < BP) s2s[tid] = g_s2p[tid * Nn + m];
    __syncthreads();

    float D[BP];
#pragma unroll
    for (int bp = 0; bp < BP; bp++) D[bp] = 0.f;

    const float* row = S + (size_t)m * Nn;
    for (int n = tid; n < Nn; n += 256) {
        float adj = row[n] + (n == m ? 1.f : 0.f);
        if (fabsf(adj) > ZTOL) {
#pragma unroll
            for (int bp = 0; bp < BP; bp++) {
                float t = s2s[bp] + g_s1p[bp * Nn + n];
                t = fmaxf(t, 0.2f * t);
                D[bp] += __expf(t);
            }
        }
    }

#pragma unroll
    for (int bp = 0; bp < BP; bp++) {
#pragma unroll
        for (int off = 16; off; off >>= 1)
            D[bp] += __shfl_down_sync(0xffffffffu, D[bp], off);
    }
    const int w = tid >> 5, l = tid & 31;
    if (l == 0) {
#pragma unroll
        for (int bp = 0; bp < BP; bp++) red[w][bp] = D[bp];
    }
    __syncthreads();
    if (tid < BP) {
        float d = 0.f;
#pragma unroll
        for (int ww = 0; ww < 8; ww++) d += red[ww][tid];
        float ci = (d > 0.f) ? 1.f / d : 0.f;
        float s2 = s2s[tid];
        g_T2n[m * BP + tid] =
            make_float4(s2, __expf(s2) * ci, __expf(0.2f * s2) * ci, 0.f);
    }
}

// ---------------------------------------------------------------------------
// K3: deterministic CSC build.
// ---------------------------------------------------------------------------
__global__ void k3_count(const float* __restrict__ S) {
    const int n = blockIdx.x * 256 + threadIdx.x;
    const int mc = blockIdx.y;
    int c = 0;
    const int m0 = mc * CHR;
#pragma unroll 8
    for (int mm = 0; mm < CHR; mm++)
        if (fabsf(S[(size_t)(m0 + mm) * Nn + n]) > ZTOL) c++;
    g_cnt[n * NCH + mc] = c;
}

__global__ void k3_offs() {   // warp per column: shuffle scan of 32 chunk counts
    const int n = blockIdx.x * 8 + (threadIdx.x >> 5);
    const int lane = threadIdx.x & 31;
    int c = g_cnt[n * NCH + lane];
    int v = c;
#pragma unroll
    for (int off = 1; off < 32; off <<= 1) {
        int u = __shfl_up_sync(0xffffffffu, v, off);
        if (lane >= off) v += u;
    }
    g_off2[n * NCH + lane] = v - c;
    if (lane == 31) g_tot[n] = v;
}

__global__ void k3_scan() {   // one block: colptr over 2048 totals
    __shared__ int s[Nn];
    const int tid = threadIdx.x;
    const int n0 = tid, n1 = tid + 1024;
    int t0 = g_tot[n0], t1 = g_tot[n1];
    s[n0] = t0; s[n1] = t1;
    __syncthreads();
    for (int off = 1; off < Nn; off <<= 1) {
        int a0 = (n0 >= off) ? s[n0 - off] : 0;
        int a1 = (n1 >= off) ? s[n1 - off] : 0;
        __syncthreads();
        s[n0] += a0; s[n1] += a1;
        __syncthreads();
    }
    g_colptr[n0] = s[n0] - t0;
    g_colptr[n1] = s[n1] - t1;
    if (tid == 1023) g_colptr[Nn] = s[Nn - 1];
}

__global__ void k3_fill(const float* __restrict__ S) {
    const int n = blockIdx.x * 256 + threadIdx.x;
    const int mc = blockIdx.y;
    int off = g_colptr[n] + g_off2[n * NCH + mc];
    const int m0 = mc * CHR;
    for (int mm = 0; mm < CHR; mm++) {
        int m = m0 + mm;
        float sv = S[(size_t)m * Nn + n];
        if (fabsf(sv) > ZTOL && off < MAXNNZ) {
            g_rv[off] = make_float2(__int_as_float(m * (Ff / 2)), sv);
            off++;
        }
    }
}

// ---------------------------------------------------------------------------
// K4: block = column n, 16 warps = bp, lanes = f-pairs. One long entry loop,
// fused weight computation, fp16 Wx gather (128B per warp-entry).
// ---------------------------------------------------------------------------
__global__ void __launch_bounds__(512) k4_out(float* __restrict__ out) {
    const int n = blockIdx.x;
    const int bp = threadIdx.x >> 5;
    const int lane = threadIdx.x & 31;

    const int lo = g_colptr[n], hi = g_colptr[n + 1];
    const float4 t1 = g_T1n[n * BP + bp];
    const __half2* __restrict__ wxh = g_Wxh + (size_t)bp * Nn * (Ff / 2);
    const float4* __restrict__ t2tab = g_T2n;
    const float2* __restrict__ rv = g_rv;

    float a0 = 0.f, a1 = 0.f;
#pragma unroll 4
    for (int i = lo; i < hi; i++) {
        float2 e = rv[i];
        int mo = __float_as_int(e.x);            // m * 32
        float4 t2 = t2tab[mo >> 1 | bp];         // m*16 + bp (exact: low bits 0)
        float t = t1.x + t2.x;
        float wgt = e.y * ((t >= 0.f) ? t1.y * t2.y : t1.z * t2.z);
        float2 wx = __half22float2(wxh[mo + lane]);
        a0 = fmaf(wgt, wx.x, a0);
        a1 = fmaf(wgt, wx.y, a1);
    }

    const int b = bp >> 2, p = bp & 3;
    const size_t base = ((size_t)b * (Pp * Ff) + p * Ff) * Nn + n;
    out[base + (size_t)(2 * lane) * Nn]     = fmaxf(a0, 0.f);
    out[base + (size_t)(2 * lane + 1) * Nn] = fmaxf(a1, 0.f);
}

// ---------------------------------------------------------------------------
// Launch order puts k2 at position 4 (ncu captures the 4th launch).
// ---------------------------------------------------------------------------
extern "C" void kernel_launch(void* const* d_in, const int* in_sizes, int n_in,
                              void* d_out, int out_size) {
    const float* x = (const float*)d_in[0];
    const float* a = (const float*)d_in[1];
    const float* W = (const float*)d_in[2];
    const float* S = (const float*)d_in[3];
    float* out = (float*)d_out;

    k1_wx<<<dim3(8, Pp, Bb), 256>>>(x, a, W);
    k3_count<<<dim3(8, NCH), 256>>>(S);
    k3_offs<<<256, 256>>>();
    k2_rowstats<<<Nn, 256>>>(S);       // 4th launch -> profiled
    k3_scan<<<1, 1024>>>();
    k3_fill<<<dim3(8, NCH), 256>>>(S);
    k4_out<<<Nn, 512>>>(out);
}

// round 8
// speedup vs baseline: 2.6369x; 1.4720x over previous
#include <cuda_runtime.h>
#include <cuda_fp16.h>
#include <math.h>

#define Bb 4
#define Gg 128
#define Nn 2048
#define Pp 4
#define Ff 64
#define BP 16
#define ZTOL 1e-9f
#define NCH 32          // 32 chunks of 64 rows
#define CHR 64
#define MAXNNZ (1 << 19)
#define MAXE 256        // entries staged per k4 chunk

// ---------------- scratch ----------------
__device__ __align__(16) __half2 g_Wxh[BP * Nn * (Ff / 2)];  // [bp][m][f/2] 4MB
__device__ __align__(16) float4  g_T1n[Nn * BP];  // [n][bp]: (s1, e^{s1}, e^{.2 s1}, 0)
__device__ __align__(16) float4  g_T2n[Nn * BP];  // [m][bp]: (s2, e^{s2}/D, e^{.2 s2}/D, 0)
__device__ float g_s1t[Nn * BP + 32];             // [n][bp] transposed plane (+pad)
__device__ float g_s2p[BP * Nn];                  // [bp][n] plane
__device__ int   g_cnt[Nn * NCH];
__device__ int   g_off2[Nn * NCH];
__device__ int   g_tot[Nn];
__device__ int   g_colptr[Nn + 1];
__device__ __align__(16) float2 g_rv[MAXNNZ];     // (bits of m*32, S value), col-major

// ---------------------------------------------------------------------------
// K1: Wx = W @ x per (b,p) -> fp16; s1/s2 planes + T1 exp table.
// ---------------------------------------------------------------------------
__global__ void k1_wx(const float* __restrict__ x, const float* __restrict__ a,
                      const float* __restrict__ W) {
    const int b = blockIdx.z, p = blockIdx.y;
    const int n = blockIdx.x * 256 + threadIdx.x;

    __shared__ __align__(16) float Ws[Gg * Ff];
    __shared__ float as[2 * Ff];

    for (int i = threadIdx.x; i < Gg * Ff; i += 256) {
        int f = i >> 7, g = i & 127;
        Ws[g * Ff + f] = W[(p * Ff + f) * Gg + g];
    }
    if (threadIdx.x < 2 * Ff) as[threadIdx.x] = a[p * 2 * Ff + threadIdx.x];
    __syncthreads();

    float4 acc[16];
#pragma unroll
    for (int i = 0; i < 16; i++) acc[i] = make_float4(0.f, 0.f, 0.f, 0.f);

    const float* xb = x + ((size_t)b * Gg) * Nn + n;
    const float4* Ws4 = (const float4*)Ws;

    for (int g = 0; g < Gg; g++) {
        float xv = xb[(size_t)g * Nn];
#pragma unroll
        for (int i = 0; i < 16; i++) {
            float4 w = Ws4[g * 16 + i];
            acc[i].x += w.x * xv; acc[i].y += w.y * xv;
            acc[i].z += w.z * xv; acc[i].w += w.w * xv;
        }
    }

    const int bp = b * Pp + p;
    __half2* dsth = g_Wxh + (size_t)(bp * Nn + n) * (Ff / 2);
    float s1 = 0.f, s2 = 0.f;
#pragma unroll
    for (int i = 0; i < 16; i++) {
        dsth[2 * i]     = __floats2half2_rn(acc[i].x, acc[i].y);
        dsth[2 * i + 1] = __floats2half2_rn(acc[i].z, acc[i].w);
        s1 += as[4*i+0]*acc[i].x + as[4*i+1]*acc[i].y + as[4*i+2]*acc[i].z + as[4*i+3]*acc[i].w;
        s2 += as[Ff+4*i+0]*acc[i].x + as[Ff+4*i+1]*acc[i].y + as[Ff+4*i+2]*acc[i].z + as[Ff+4*i+3]*acc[i].w;
    }
    g_s1t[n * BP + bp] = s1;
    g_s2p[bp * Nn + n] = s2;
    g_T1n[n * BP + bp] = make_float4(s1, __expf(s1), __expf(0.2f * s1), 0.f);
}

// ---------------------------------------------------------------------------
// K2: block per row m; ballot-compressed masked scan. For each masked entry,
// lanes 0-15 (= bp) load a coalesced 64B s1 vector and accumulate exp.
// ---------------------------------------------------------------------------
__global__ void k2_rowstats(const float* __restrict__ S) {
    const int m = blockIdx.x;
    const int tid = threadIdx.x;
    const int w = tid >> 5, lane = tid & 31;

    __shared__ float red[8][BP];

    const float s2l = g_s2p[(lane & 15) * Nn + m];   // lane>=16 duplicates, unused
    float D = 0.f;
    const float* row = S + (size_t)m * Nn;

#pragma unroll
    for (int pass = 0; pass < Nn / 256; pass++) {
        const int base = pass * 256 + w * 32;
        const int n = base + lane;
        float adj = row[n] + (n == m ? 1.f : 0.f);
        unsigned msk = __ballot_sync(0xffffffffu, fabsf(adj) > ZTOL);
        while (msk) {
            int j = __ffs(msk) - 1;
            msk &= msk - 1;
            int ne = base + j;
            float s1 = g_s1t[ne * BP + lane];        // 64B coalesced (lanes 0-15)
            float t = s2l + s1;
            t = fmaxf(t, 0.2f * t);
            D += __expf(t);
        }
    }

    if (lane < BP) red[w][lane] = D;
    __syncthreads();
    if (tid < BP) {
        float d = 0.f;
#pragma unroll
        for (int ww = 0; ww < 8; ww++) d += red[ww][tid];
        float ci = (d > 0.f) ? 1.f / d : 0.f;
        float s2 = g_s2p[tid * Nn + m];
        g_T2n[m * BP + tid] =
            make_float4(s2, __expf(s2) * ci, __expf(0.2f * s2) * ci, 0.f);
    }
}

// ---------------------------------------------------------------------------
// K3: deterministic CSC build.
// ---------------------------------------------------------------------------
__global__ void k3_count(const float* __restrict__ S) {
    const int n = blockIdx.x * 256 + threadIdx.x;
    const int mc = blockIdx.y;
    int c = 0;
    const int m0 = mc * CHR;
#pragma unroll 8
    for (int mm = 0; mm < CHR; mm++)
        if (fabsf(S[(size_t)(m0 + mm) * Nn + n]) > ZTOL) c++;
    g_cnt[n * NCH + mc] = c;
}

__global__ void k3_offs() {   // warp per column: shuffle scan of 32 chunk counts
    const int n = blockIdx.x * 8 + (threadIdx.x >> 5);
    const int lane = threadIdx.x & 31;
    int c = g_cnt[n * NCH + lane];
    int v = c;
#pragma unroll
    for (int off = 1; off < 32; off <<= 1) {
        int u = __shfl_up_sync(0xffffffffu, v, off);
        if (lane >= off) v += u;
    }
    g_off2[n * NCH + lane] = v - c;
    if (lane == 31) g_tot[n] = v;
}

__global__ void k3_scan() {   // one block: colptr over 2048 totals
    __shared__ int s[Nn];
    const int tid = threadIdx.x;
    const int n0 = tid, n1 = tid + 1024;
    int t0 = g_tot[n0], t1 = g_tot[n1];
    s[n0] = t0; s[n1] = t1;
    __syncthreads();
    for (int off = 1; off < Nn; off <<= 1) {
        int a0 = (n0 >= off) ? s[n0 - off] : 0;
        int a1 = (n1 >= off) ? s[n1 - off] : 0;
        __syncthreads();
        s[n0] += a0; s[n1] += a1;
        __syncthreads();
    }
    g_colptr[n0] = s[n0] - t0;
    g_colptr[n1] = s[n1] - t1;
    if (tid == 1023) g_colptr[Nn] = s[Nn - 1];
}

__global__ void k3_fill(const float* __restrict__ S) {
    const int n = blockIdx.x * 256 + threadIdx.x;
    const int mc = blockIdx.y;
    int off = g_colptr[n] + g_off2[n * NCH + mc];
    const int m0 = mc * CHR;
    for (int mm = 0; mm < CHR; mm++) {
        int m = m0 + mm;
        float sv = S[(size_t)m * Nn + n];
        if (fabsf(sv) > ZTOL && off < MAXNNZ) {
            g_rv[off] = make_float2(__int_as_float(m * (Ff / 2)), sv);
            off++;
        }
    }
}

// ---------------------------------------------------------------------------
// K4: block = column n. Phase A: 512 threads cooperatively compute all
// (entry, bp) weights into smem (coalesced T2 loads, 16x less issue than
// per-warp broadcast arithmetic). Phase B: warp bp streams entries:
// LDS.64 (mo,wgt) -> independent LDG wx -> 2 FFMA (max MLP).
// ---------------------------------------------------------------------------
__global__ void __launch_bounds__(512) k4_out(float* __restrict__ out) {
    __shared__ __align__(16) float2 s_rv[MAXE];          // 2KB
    __shared__ __align__(16) float2 s_w2[MAXE * BP];     // 32KB: (mo bits, wgt)
    __shared__ __align__(16) float4 s_t1[BP];

    const int n = blockIdx.x;
    const int tid = threadIdx.x;
    const int bp = tid >> 5, lane = tid & 31;

    if (tid < BP) s_t1[tid] = g_T1n[n * BP + tid];

    const int lo = g_colptr[n], hi = g_colptr[n + 1];
    const __half2* __restrict__ wxh = g_Wxh + (size_t)bp * Nn * (Ff / 2);
    const float4* __restrict__ t2tab = g_T2n;
    const float2* __restrict__ rv = g_rv;

    float a0 = 0.f, a1 = 0.f;

    for (int base = lo; base < hi; base += MAXE) {
        const int cnt = min(hi - base, MAXE);
        if (tid < cnt) s_rv[tid] = rv[base + tid];
        __syncthreads();

        // Phase A: weights for all (j, bp) pairs.
        for (int idx = tid; idx < cnt * BP; idx += 512) {
            int j = idx >> 4, bpa = idx & 15;
            float2 e = s_rv[j];
            int mo = __float_as_int(e.x);                // m * 32
            float4 t2 = t2tab[(mo >> 1) | bpa];          // m*16 + bpa
            float4 t1 = s_t1[bpa];
            float t = t1.x + t2.x;
            float wgt = e.y * ((t >= 0.f) ? t1.y * t2.y : t1.z * t2.z);
            s_w2[idx] = make_float2(e.x, wgt);
        }
        __syncthreads();

        // Phase B: gather-accumulate per (bp-warp, f-pair-lane).
        const float2* wrow = s_w2 + bp;
#pragma unroll 4
        for (int j = 0; j < cnt; j++) {
            float2 mw = wrow[j * BP];
            int mo = __float_as_int(mw.x);
            float2 wx = __half22float2(wxh[mo + lane]);
            a0 = fmaf(mw.y, wx.x, a0);
            a1 = fmaf(mw.y, wx.y, a1);
        }
        __syncthreads();
    }

    const int b = bp >> 2, p = bp & 3;
    const size_t obase = ((size_t)b * (Pp * Ff) + p * Ff) * Nn + n;
    out[obase + (size_t)(2 * lane) * Nn]     = fmaxf(a0, 0.f);
    out[obase + (size_t)(2 * lane + 1) * Nn] = fmaxf(a1, 0.f);
}

// ---------------------------------------------------------------------------
// k2 kept at 4th launch (profiled) to verify the ballot-compression win.
// ---------------------------------------------------------------------------
extern "C" void kernel_launch(void* const* d_in, const int* in_sizes, int n_in,
                              void* d_out, int out_size) {
    const float* x = (const float*)d_in[0];
    const float* a = (const float*)d_in[1];
    const float* W = (const float*)d_in[2];
    const float* S = (const float*)d_in[3];
    float* out = (float*)d_out;

    k1_wx<<<dim3(8, Pp, Bb), 256>>>(x, a, W);
    k3_count<<<dim3(8, NCH), 256>>>(S);
    k3_offs<<<256, 256>>>();
    k2_rowstats<<<Nn, 256>>>(S);       // 4th launch -> profiled
    k3_scan<<<1, 1024>>>();
    k3_fill<<<dim3(8, NCH), 256>>>(S);
    k4_out<<<Nn, 512>>>(out);
}